// round 6
// baseline (speedup 1.0000x reference)
#include <cuda_runtime.h>
#include <cuda_bf16.h>
#include <cstdint>

// Problem constants
#define Bn 512
#define Tn 512
#define En 64
#define Hn 64
#define Gn 256   // 4*H
#define Cn 8
#define Rr 2     // batch rows per LSTM block
#define PF 4     // xw prefetch depth (steps)
#define GROWS 128 // rows per GEMM block

typedef unsigned long long u64;

// Scratch (device globals: no cudaMalloc allowed)
__device__ float g_bufA[Bn * Tn * En];
__device__ float g_bufB[Bn * Tn * Hn];
__device__ float g_xw[Bn * Tn * Gn];

// ---------------------------------------------------------------------------
// packed f32x2 helpers
// ---------------------------------------------------------------------------
__device__ __forceinline__ u64 pack2(float lo, float hi) {
    u64 r; asm("mov.b64 %0, {%1, %2};" : "=l"(r) : "f"(lo), "f"(hi)); return r;
}
__device__ __forceinline__ void unpack2(u64 v, float& lo, float& hi) {
    asm("mov.b64 {%0, %1}, %2;" : "=f"(lo), "=f"(hi) : "l"(v));
}
__device__ __forceinline__ u64 fma2(u64 a, u64 b, u64 c) {
    u64 d; asm("fma.rn.f32x2 %0, %1, %2, %3;" : "=l"(d) : "l"(a), "l"(b), "l"(c));
    return d;
}

__device__ __forceinline__ float sigf(float x) {
    return 1.f / (1.f + __expf(-x));
}
__device__ __forceinline__ float tanhfast(float x) {
    return 2.f / (1.f + __expf(-2.f * x)) - 1.f;
}

// ---------------------------------------------------------------------------
// Embedding
// ---------------------------------------------------------------------------
__global__ void embed_kernel(const int* __restrict__ ids,
                             const float* __restrict__ wt,
                             const float* __restrict__ pt,
                             float* __restrict__ out)
{
    int i = blockIdx.x * blockDim.x + threadIdx.x;
    int bt = i >> 4;
    int v  = i & 15;
    int id = ids[bt];
    int t  = bt & (Tn - 1);
    float4 a = ((const float4*)wt)[id * 16 + v];
    float4 p = ((const float4*)pt)[t * 16 + v];
    float4 r;
    r.x = a.x + p.x; r.y = a.y + p.y; r.z = a.z + p.z; r.w = a.w + p.w;
    ((float4*)out)[i] = r;
}

// ---------------------------------------------------------------------------
// XW GEMM: XW[row][j] = sum_k X[row][k] * Wx[k][j] + b[j]
// 1 output column per thread (64 weight regs -> ~95 total regs ->
// 2 blocks/SM, 16 warps/SM). 128 rows per block; X tile in shared,
// broadcast LDS.128 feeding 2 FFMA2 each.
// ---------------------------------------------------------------------------
__global__ void __launch_bounds__(256, 2)
gemm_xw_kernel(const float* __restrict__ X,
               const float* __restrict__ Wx,
               const float* __restrict__ bias,
               float* __restrict__ XW)
{
    const int j    = threadIdx.x;
    const int rowB = blockIdx.x * GROWS;

    __shared__ __align__(16) float xs[GROWS * 64];   // 32 KB

    // weight column j packed along k
    u64 wp[32];
#pragma unroll
    for (int m = 0; m < 32; m++)
        wp[m] = pack2(Wx[(2 * m) * Gn + j], Wx[(2 * m + 1) * Gn + j]);
    const float bj = bias[j];

    // cooperative load GROWS x 64 floats = 2048 float4
    const float4* Xv = (const float4*)(X + (size_t)rowB * En);
    float4* xs4 = (float4*)xs;
#pragma unroll
    for (int i = 0; i < (GROWS * 16) / 256; i++)
        xs4[j + i * 256] = Xv[j + i * 256];
    __syncthreads();

    float* outp = XW + (size_t)rowB * Gn + j;
#pragma unroll 2
    for (int r = 0; r < GROWS; r++) {
        const ulonglong2* xr = (const ulonglong2*)&xs[r * 64];
        u64 a0 = pack2(bj, 0.f), a1 = 0ull;
#pragma unroll
        for (int kv = 0; kv < 16; kv++) {
            ulonglong2 v = xr[kv];
            a0 = fma2(wp[2 * kv],     v.x, a0);
            a1 = fma2(wp[2 * kv + 1], v.y, a1);
        }
        float p, q, s, t2;
        unpack2(a0, p, q); unpack2(a1, s, t2);
        outp[(size_t)r * Gn] = (p + q) + (s + t2);
    }
}

// ---------------------------------------------------------------------------
// LSTM recurrence. Rr=2 rows/block -> grid 256 blocks, 2 blocks/SM
// (independent blocks overlap each other's barrier/gate phases).
// Thread j = column j; gate phase uses threads with (j & 64) == 0:
// j in [0,64) -> row 0, j in [128,192) -> row 1.
// ---------------------------------------------------------------------------
#define LSTM_STEP(T, RING)                                                    \
{                                                                             \
    u64 acc0[Rr], acc1[Rr];                                                   \
    _Pragma("unroll")                                                         \
    for (int r = 0; r < Rr; r++) {                                            \
        acc0[r] = pack2(RING[r], 0.f);                                        \
        acc1[r] = 0ull;                                                       \
    }                                                                         \
    {                                                                         \
        const int tl = (T) + PF;                                              \
        if (tl < Tn) {                                                        \
            _Pragma("unroll")                                                 \
            for (int r = 0; r < Rr; r++)                                      \
                RING[r] = xp[r][(size_t)tl * Gn];                             \
        }                                                                     \
    }                                                                         \
    _Pragma("unroll")                                                         \
    for (int kv = 0; kv < 16; kv++) {                                         \
        const u64 w0 = wp[2 * kv];                                            \
        const u64 w1 = wp[2 * kv + 1];                                        \
        _Pragma("unroll")                                                     \
        for (int r = 0; r < Rr; r++) {                                        \
            ulonglong2 hv = *(const ulonglong2*)&hs[r][4 * kv];               \
            acc0[r] = fma2(w0, hv.x, acc0[r]);                                \
            acc1[r] = fma2(w1, hv.y, acc1[r]);                                \
        }                                                                     \
    }                                                                         \
    _Pragma("unroll")                                                         \
    for (int r = 0; r < Rr; r++) {                                            \
        float a_, b_, c_, d_;                                                 \
        unpack2(acc0[r], a_, b_);                                             \
        unpack2(acc1[r], c_, d_);                                             \
        zs[r][j] = (a_ + b_) + (c_ + d_);                                     \
    }                                                                         \
    __syncthreads();                                                          \
    if (gate_active) {                                                        \
        float zi = zs[rp][hh];                                                \
        float zf = zs[rp][64  + hh];                                          \
        float zg = zs[rp][128 + hh];                                          \
        float zo = zs[rp][192 + hh];                                          \
        float ig = sigf(zi);                                                  \
        float fg = sigf(zf);                                                  \
        float gg = tanhfast(zg);                                              \
        float og = sigf(zo);                                                  \
        c = fg * c + ig * gg;                                                 \
        float h = og * tanhfast(c);                                           \
        hs[rp][hh] = h;                                                       \
        hrow[(size_t)(T) * Hn] = h;                                           \
    }                                                                         \
    __syncthreads();                                                          \
}

__global__ void __launch_bounds__(256, 2)
lstm_kernel(const float* __restrict__ xw,   // [B*T, 256]
            const float* __restrict__ Wh,   // [64, 256]
            float* __restrict__ hout)       // [B*T, 64]
{
    const int j  = threadIdx.x;
    const int b0 = blockIdx.x * Rr;
    const int rp = j >> 7;               // gate-phase row (0/1)
    const int hh = j & 63;               // gate-phase hidden index
    const bool gate_active = (j & 64) == 0;

    __shared__ __align__(16) float hs[Rr][Hn];
    __shared__ float zs[Rr][Gn];

    u64 wp[32];
#pragma unroll
    for (int m = 0; m < 32; m++)
        wp[m] = pack2(Wh[(2 * m) * Gn + j], Wh[(2 * m + 1) * Gn + j]);

    if (j < Rr * Hn) hs[j >> 6][j & 63] = 0.f;
    float c = 0.f;

    const float* xp[Rr];
#pragma unroll
    for (int r = 0; r < Rr; r++)
        xp[r] = xw + (size_t)(b0 + r) * Tn * Gn + j;

    // prime the 4-slot ring with t = 0..3
    float ringA[Rr], ringB[Rr], ringC[Rr], ringD[Rr];
#pragma unroll
    for (int r = 0; r < Rr; r++) {
        ringA[r] = xp[r][(size_t)0 * Gn];
        ringB[r] = xp[r][(size_t)1 * Gn];
        ringC[r] = xp[r][(size_t)2 * Gn];
        ringD[r] = xp[r][(size_t)3 * Gn];
    }

    float* hrow = hout + (size_t)(b0 + rp) * Tn * Hn + hh;

    __syncthreads();

    for (int tb = 0; tb < Tn; tb += PF) {
        LSTM_STEP(tb + 0, ringA);
        LSTM_STEP(tb + 1, ringB);
        LSTM_STEP(tb + 2, ringC);
        LSTM_STEP(tb + 3, ringD);
    }
}

// ---------------------------------------------------------------------------
// Logits + softmax, duplicated into both time halves (bwd == fwd).
// ---------------------------------------------------------------------------
__global__ void __launch_bounds__(256)
logits_kernel(const float* __restrict__ Hs,
              const float* __restrict__ Wd,
              const float* __restrict__ bd,
              float* __restrict__ out)
{
    __shared__ float wd_s[Hn * Cn];
    __shared__ float bd_s[Cn];
    const int tid = threadIdx.x;
    for (int i = tid; i < Hn * Cn; i += 256) wd_s[i] = Wd[i];
    if (tid < Cn) bd_s[tid] = bd[tid];
    __syncthreads();

    const int row = blockIdx.x * 256 + tid;
    float acc[Cn];
#pragma unroll
    for (int cc = 0; cc < Cn; cc++) acc[cc] = bd_s[cc];

    const float4* hr = (const float4*)(Hs + (size_t)row * Hn);
#pragma unroll
    for (int kv = 0; kv < 16; kv++) {
        float4 x = hr[kv];
#pragma unroll
        for (int cc = 0; cc < Cn; cc++) {
            acc[cc] += x.x * wd_s[(4*kv+0) * Cn + cc];
            acc[cc] += x.y * wd_s[(4*kv+1) * Cn + cc];
            acc[cc] += x.z * wd_s[(4*kv+2) * Cn + cc];
            acc[cc] += x.w * wd_s[(4*kv+3) * Cn + cc];
        }
    }

    float m = acc[0];
#pragma unroll
    for (int cc = 1; cc < Cn; cc++) m = fmaxf(m, acc[cc]);
    float s = 0.f;
    float e[Cn];
#pragma unroll
    for (int cc = 0; cc < Cn; cc++) { e[cc] = __expf(acc[cc] - m); s += e[cc]; }
    float inv = 1.f / s;

    const int b = row >> 9;
    const int t = row & (Tn - 1);
    float4 r0, r1;
    r0.x = e[0]*inv; r0.y = e[1]*inv; r0.z = e[2]*inv; r0.w = e[3]*inv;
    r1.x = e[4]*inv; r1.y = e[5]*inv; r1.z = e[6]*inv; r1.w = e[7]*inv;

    float* o1 = out + ((size_t)b * (2 * Tn) + t) * Cn;
    float* o2 = o1 + (size_t)Tn * Cn;
    ((float4*)o1)[0] = r0; ((float4*)o1)[1] = r1;
    ((float4*)o2)[0] = r0; ((float4*)o2)[1] = r1;
}

// ---------------------------------------------------------------------------
// Launch
// ---------------------------------------------------------------------------
extern "C" void kernel_launch(void* const* d_in, const int* in_sizes, int n_in,
                              void* d_out, int out_size)
{
    const int*   ids        = (const int*)d_in[0];
    const float* word_table = (const float*)d_in[3];
    const float* pos_table  = (const float*)d_in[4];
    const float* Wx         = (const float*)d_in[5];
    const float* Wh         = (const float*)d_in[6];
    const float* b          = (const float*)d_in[7];
    const float* Wd         = (const float*)d_in[8];
    const float* bd         = (const float*)d_in[9];
    float* out = (float*)d_out;

    float *bufA, *bufB, *xwp;
    cudaGetSymbolAddress((void**)&bufA, g_bufA);
    cudaGetSymbolAddress((void**)&bufB, g_bufB);
    cudaGetSymbolAddress((void**)&xwp,  g_xw);

    embed_kernel<<<(Bn * Tn * 16) / 256, 256>>>(ids, word_table, pos_table, bufA);

    gemm_xw_kernel<<<(Bn * Tn) / GROWS, 256>>>(bufA, Wx, b, xwp);
    lstm_kernel<<<Bn / Rr, 256>>>(xwp, Wh, bufB);

    gemm_xw_kernel<<<(Bn * Tn) / GROWS, 256>>>(bufB, Wx, b, xwp);
    lstm_kernel<<<Bn / Rr, 256>>>(xwp, Wh, bufA);

    logits_kernel<<<(Bn * Tn) / 256, 256>>>(bufA, Wd, bd, out);
}